// round 2
// baseline (speedup 1.0000x reference)
#include <cuda_runtime.h>
#include <cuda_bf16.h>
#include <cstdint>

// ---------------------------------------------------------------------------
// Shapes (fixed by the problem)
// ---------------------------------------------------------------------------
#define NB   32        // batch
#define HW   4096      // 64*64 pixels
#define FC   256       // feature channels
#define OD   128       // hidden dense
#define O2   256       // dense out channels
#define HSP  128       // hidden sparse
#define NT   8         // num tokens
#define KS_SPLIT 4     // split-K factor for sparse GEMM

#define DENSE_TOTAL ((size_t)NB * O2 * HW)   // 33,554,432 floats

// ---------------------------------------------------------------------------
// Scratch (device globals; no runtime allocation)
// ---------------------------------------------------------------------------
__device__ float g_scale[NB * HW];                 // 1 + sim
__device__ float g_w1t[FC * OD];                   // w_dense1 transposed: [c][o]
__device__ float g_w2t[OD * O2];                   // w_dense2 transposed: [o][o2]
__device__ float g_ws1t[HW * HSP];                 // w_sparse1 transposed: [p][o]
__device__ float g_hsp[(size_t)KS_SPLIT * NB * HSP * FC];  // split-K partials
__device__ float g_hs[(size_t)NB * HSP * FC];      // relu(sparse layer1)

// ---------------------------------------------------------------------------
// K0a: scale[b,p] = 1 + dot(feat[b,p,:], proto)   (warp per pixel)
// ---------------------------------------------------------------------------
__global__ void k_scale(const float* __restrict__ feat,
                        const float* __restrict__ proto)
{
    __shared__ float pr[FC];
    const int t = threadIdx.x;
    pr[t] = proto[t];
    __syncthreads();

    const int warp = t >> 5, lane = t & 31;
    const int pix  = blockIdx.x * 8 + warp;          // 16384 blocks * 8 warps
    const float4* f4 = reinterpret_cast<const float4*>(feat + (size_t)pix * FC);

    float4 a = f4[lane];
    float4 b = f4[lane + 32];
    const int c0 = lane * 4;
    float s = a.x * pr[c0] + a.y * pr[c0 + 1] + a.z * pr[c0 + 2] + a.w * pr[c0 + 3]
            + b.x * pr[128 + c0] + b.y * pr[128 + c0 + 1]
            + b.z * pr[128 + c0 + 2] + b.w * pr[128 + c0 + 3];
    #pragma unroll
    for (int off = 16; off > 0; off >>= 1)
        s += __shfl_xor_sync(0xFFFFFFFFu, s, off);
    if (lane == 0) g_scale[pix] = 1.0f + s;
}

// ---------------------------------------------------------------------------
// K0b: transpose the three weight matrices (reads coalesced, writes strided)
// ---------------------------------------------------------------------------
__global__ void k_prep(const float* __restrict__ w_d1,
                       const float* __restrict__ w_d2,
                       const float* __restrict__ w_s1)
{
    const int i = blockIdx.x * 256 + threadIdx.x;
    if (i < OD * FC) {                                    // 32768
        const int o = i >> 8, c = i & 255;                // w_d1[o][c]
        g_w1t[c * OD + o] = w_d1[i];
    } else if (i < 2 * OD * FC) {                         // next 32768
        const int j = i - OD * FC;
        const int o2 = j >> 7, o = j & 127;               // w_d2[o2][o]
        g_w2t[o * O2 + o2] = w_d2[j];
    } else {
        const int j = i - 2 * OD * FC;
        if (j < HSP * HW) {                               // 524288
            const int o = j >> 12, p = j & 4095;          // w_s1[o][p]
            g_ws1t[p * HSP + o] = w_s1[j];
        }
    }
}

// ---------------------------------------------------------------------------
// K2: dense path. One block = 128 pixels of one batch.
//   GEMM1: [128p x 256c] * [256c x 128o] -> relu -> Hs[o][p] (smem)
//   GEMM2: [128p x 128o] * [128o x 256o2] -> out[b][o2][p]
// Double-buffered smem, 8x8 register tiles, float4 LDS.
// dyn smem: As 2x1024f | Bs 2x1024f | Hs 128x132f  = 83968 B
// ---------------------------------------------------------------------------
#define HPAD 132

__global__ void __launch_bounds__(256)
k_dense(const float* __restrict__ feat, const float* __restrict__ b1,
        const float* __restrict__ b2, float* __restrict__ out)
{
    extern __shared__ float sm[];
    float* As = sm;            // [2][8][128]   (k=c rows, m=p cols)
    float* Bs = sm + 2048;     // [2][8][128]   (k=c rows, n=o cols)
    float* Hs = sm + 4096;     // [128o][132p]

    const int tid = threadIdx.x;
    const int bb  = blockIdx.x >> 5;
    const int p0  = (blockIdx.x & 31) << 7;
    const float* fbase = feat + ((size_t)bb * HW + p0) * FC;

    const int tx = tid & 15, ty = tid >> 4;
    const int tx4 = tx * 4,  ty4 = ty * 4;
    const int lp = tid >> 1, lh = tid & 1;           // A-load mapping
    const float sc = __ldg(&g_scale[bb * HW + p0 + lp]);
    const float4* frow = reinterpret_cast<const float4*>(fbase + (size_t)lp * FC);

    float c1[8][8];
    #pragma unroll
    for (int i = 0; i < 8; ++i)
        #pragma unroll
        for (int j = 0; j < 8; ++j) c1[i][j] = 0.f;

    // ---- GEMM1, K=256 in 32 chunks of 8, double-buffered ----
    float4 ra = frow[lh];
    float4 rb = reinterpret_cast<const float4*>(g_w1t)[tid];
    {
        float* Ad = As;
        Ad[(4 * lh + 0) * 128 + lp] = ra.x * sc;
        Ad[(4 * lh + 1) * 128 + lp] = ra.y * sc;
        Ad[(4 * lh + 2) * 128 + lp] = ra.z * sc;
        Ad[(4 * lh + 3) * 128 + lp] = ra.w * sc;
        reinterpret_cast<float4*>(Bs)[tid] = rb;
    }
    __syncthreads();
    int buf = 0;
    for (int it = 0; it < 32; ++it) {
        if (it < 31) {
            ra = frow[2 * (it + 1) + lh];
            rb = reinterpret_cast<const float4*>(g_w1t + (it + 1) * 8 * 128)[tid];
        }
        const float* A  = As + buf * 1024;
        const float* Bb = Bs + buf * 1024;
        #pragma unroll
        for (int k = 0; k < 8; ++k) {
            const float4 a0 = *reinterpret_cast<const float4*>(&A[k * 128 + tx4]);
            const float4 a1 = *reinterpret_cast<const float4*>(&A[k * 128 + tx4 + 64]);
            const float4 b0 = *reinterpret_cast<const float4*>(&Bb[k * 128 + ty4]);
            const float4 b1v = *reinterpret_cast<const float4*>(&Bb[k * 128 + ty4 + 64]);
            const float av[8] = {a0.x, a0.y, a0.z, a0.w, a1.x, a1.y, a1.z, a1.w};
            const float bv[8] = {b0.x, b0.y, b0.z, b0.w, b1v.x, b1v.y, b1v.z, b1v.w};
            #pragma unroll
            for (int i = 0; i < 8; ++i)
                #pragma unroll
                for (int j = 0; j < 8; ++j)
                    c1[i][j] = fmaf(av[i], bv[j], c1[i][j]);
        }
        if (it < 31) {
            buf ^= 1;
            float* Ad = As + buf * 1024;
            Ad[(4 * lh + 0) * 128 + lp] = ra.x * sc;
            Ad[(4 * lh + 1) * 128 + lp] = ra.y * sc;
            Ad[(4 * lh + 2) * 128 + lp] = ra.z * sc;
            Ad[(4 * lh + 3) * 128 + lp] = ra.w * sc;
            reinterpret_cast<float4*>(Bs + buf * 1024)[tid] = rb;
        }
        __syncthreads();
    }

    // ---- epilogue 1: relu + bias, store transposed into Hs[o][p] ----
    #pragma unroll
    for (int j = 0; j < 8; ++j) {
        const int o = (j < 4) ? (ty4 + j) : (64 + ty4 + j - 4);
        const float bias = __ldg(&b1[o]);
        #pragma unroll
        for (int i = 0; i < 8; ++i) {
            const int p = (i < 4) ? (tx4 + i) : (64 + tx4 + i - 4);
            Hs[o * HPAD + p] = fmaxf(c1[i][j] + bias, 0.f);
        }
    }
    __syncthreads();

    // ---- GEMM2: two passes of 128 output channels, K=128 in 16 chunks ----
    float* Bs2 = sm;                                 // alias As/Bs region
    const int r = tid >> 5, c4v = tid & 31;          // B2-load mapping
    #pragma unroll 1
    for (int pass = 0; pass < 2; ++pass) {
        const int n0 = pass << 7;
        float c2[8][8];
        #pragma unroll
        for (int i = 0; i < 8; ++i)
            #pragma unroll
            for (int j = 0; j < 8; ++j) c2[i][j] = 0.f;

        float4 rb2 = reinterpret_cast<const float4*>(g_w2t + r * O2 + n0)[c4v];
        reinterpret_cast<float4*>(Bs2 + r * 128)[c4v] = rb2;
        __syncthreads();
        int bf = 0;
        for (int it = 0; it < 16; ++it) {
            if (it < 15)
                rb2 = reinterpret_cast<const float4*>(g_w2t + ((it + 1) * 8 + r) * O2 + n0)[c4v];
            const float* Bb = Bs2 + bf * 1024;
            #pragma unroll
            for (int k = 0; k < 8; ++k) {
                const int ko = it * 8 + k;
                const float4 a0 = *reinterpret_cast<const float4*>(&Hs[ko * HPAD + tx4]);
                const float4 a1 = *reinterpret_cast<const float4*>(&Hs[ko * HPAD + tx4 + 64]);
                const float4 b0 = *reinterpret_cast<const float4*>(&Bb[k * 128 + ty4]);
                const float4 b1v = *reinterpret_cast<const float4*>(&Bb[k * 128 + ty4 + 64]);
                const float av[8] = {a0.x, a0.y, a0.z, a0.w, a1.x, a1.y, a1.z, a1.w};
                const float bv[8] = {b0.x, b0.y, b0.z, b0.w, b1v.x, b1v.y, b1v.z, b1v.w};
                #pragma unroll
                for (int i = 0; i < 8; ++i)
                    #pragma unroll
                    for (int j = 0; j < 8; ++j)
                        c2[i][j] = fmaf(av[i], bv[j], c2[i][j]);
            }
            if (it < 15) {
                bf ^= 1;
                reinterpret_cast<float4*>(Bs2 + bf * 1024 + r * 128)[c4v] = rb2;
            }
            __syncthreads();
        }
        // epilogue 2: out[b][o2][p]
        float* obase = out + (size_t)bb * O2 * HW + p0;
        #pragma unroll
        for (int j = 0; j < 8; ++j) {
            const int o2 = n0 + ((j < 4) ? (ty4 + j) : (64 + ty4 + j - 4));
            const float bias = __ldg(&b2[o2]);
            #pragma unroll
            for (int i = 0; i < 8; ++i) {
                const int p = (i < 4) ? (tx4 + i) : (64 + tx4 + i - 4);
                obase[(size_t)o2 * HW + p] = c2[i][j] + bias;
            }
        }
    }
}

// ---------------------------------------------------------------------------
// K3: sparse GEMM (split-K).  C[o][c] = sum_p ws1[o][p] * feat[b][p][c]*scale
// grid (2 ctile, 4 ksplit, 32 batch); block 256; 8x8 register tiles.
// ---------------------------------------------------------------------------
__global__ void __launch_bounds__(256)
k_sparse1(const float* __restrict__ feat)
{
    __shared__ float As[2][1024];   // [k=p][m=o]
    __shared__ float Bs[2][1024];   // [k=p][n=c]
    const int tid = threadIdx.x;
    const int ct = blockIdx.x, ks = blockIdx.y, bb = blockIdx.z;
    const int c0 = ct << 7;
    const int pbase = ks << 10;
    const int tx = tid & 15, ty = tid >> 4;
    const int tx4 = tx * 4,  ty4 = ty * 4;
    const int r = tid >> 5,  c4v = tid & 31;

    const float* fb  = feat + ((size_t)bb * HW + pbase) * FC + c0;
    const float* wb  = g_ws1t + (size_t)pbase * HSP;
    const float* scb = g_scale + bb * HW + pbase;

    float acc[8][8];
    #pragma unroll
    for (int i = 0; i < 8; ++i)
        #pragma unroll
        for (int j = 0; j < 8; ++j) acc[i][j] = 0.f;

    float4 ra = reinterpret_cast<const float4*>(wb)[tid];
    float  sc = __ldg(&scb[r]);
    float4 rbv = reinterpret_cast<const float4*>(fb + (size_t)r * FC)[c4v];
    rbv.x *= sc; rbv.y *= sc; rbv.z *= sc; rbv.w *= sc;
    reinterpret_cast<float4*>(&As[0][0])[tid] = ra;
    reinterpret_cast<float4*>(&Bs[0][r * 128])[c4v] = rbv;
    __syncthreads();
    int buf = 0;
    for (int it = 0; it < 128; ++it) {
        if (it < 127) {
            const int p1 = (it + 1) * 8;
            ra = reinterpret_cast<const float4*>(wb + (size_t)p1 * HSP)[tid];
            sc = __ldg(&scb[p1 + r]);
            rbv = reinterpret_cast<const float4*>(fb + (size_t)(p1 + r) * FC)[c4v];
            rbv.x *= sc; rbv.y *= sc; rbv.z *= sc; rbv.w *= sc;
        }
        const float* A  = As[buf];
        const float* Bb = Bs[buf];
        #pragma unroll
        for (int k = 0; k < 8; ++k) {
            const float4 a0 = *reinterpret_cast<const float4*>(&A[k * 128 + ty4]);
            const float4 a1 = *reinterpret_cast<const float4*>(&A[k * 128 + ty4 + 64]);
            const float4 b0 = *reinterpret_cast<const float4*>(&Bb[k * 128 + tx4]);
            const float4 b1v = *reinterpret_cast<const float4*>(&Bb[k * 128 + tx4 + 64]);
            const float av[8] = {a0.x, a0.y, a0.z, a0.w, a1.x, a1.y, a1.z, a1.w};
            const float bv[8] = {b0.x, b0.y, b0.z, b0.w, b1v.x, b1v.y, b1v.z, b1v.w};
            #pragma unroll
            for (int i = 0; i < 8; ++i)
                #pragma unroll
                for (int j = 0; j < 8; ++j)
                    acc[i][j] = fmaf(av[i], bv[j], acc[i][j]);
        }
        if (it < 127) {
            buf ^= 1;
            reinterpret_cast<float4*>(&As[buf][0])[tid] = ra;
            reinterpret_cast<float4*>(&Bs[buf][r * 128])[c4v] = rbv;
        }
        __syncthreads();
    }
    float* pb = g_hsp + (((size_t)ks * NB + bb) * HSP) * FC;
    #pragma unroll
    for (int i = 0; i < 8; ++i) {
        const int o = (i < 4) ? (ty4 + i) : (64 + ty4 + i - 4);
        #pragma unroll
        for (int j = 0; j < 8; ++j) {
            const int c = c0 + ((j < 4) ? (tx4 + j) : (64 + tx4 + j - 4));
            pb[(size_t)o * FC + c] = acc[i][j];
        }
    }
}

// K3r: reduce split-K partials, add bias, relu
__global__ void k_hsreduce(const float* __restrict__ b_s1)
{
    const size_t idx = (size_t)blockIdx.x * 256 + threadIdx.x;
    const size_t total = (size_t)NB * HSP * FC;
    if (idx < total) {
        float v = g_hsp[idx] + g_hsp[total + idx] + g_hsp[2 * total + idx]
                + g_hsp[3 * total + idx];
        const int o = (int)((idx >> 8) & 127);
        g_hs[idx] = fmaxf(v + __ldg(&b_s1[o]), 0.f);
    }
}

// K4: sparse layer 2 + embeddings.  One block per batch, thread per channel.
// cls_ids may be int32 or int64 (jax_enable_x64); detect the layout: positive
// small class ids in int64 little-endian have all odd 32-bit words == 0,
// genuine int32 ids are >= 1 everywhere.
__global__ void k_sparse2(const float* __restrict__ ws2,
                          const float* __restrict__ bs2,
                          const float* __restrict__ e_neg,
                          const float* __restrict__ e_pos,
                          const int* __restrict__ cls_ids,
                          float* __restrict__ out)
{
    __shared__ float w[NT][HSP];
    const int bb = blockIdx.x, c = threadIdx.x;
    for (int i = threadIdx.x; i < NT * HSP; i += 256)
        w[i >> 7][i & 127] = ws2[i];
    __syncthreads();

    const bool is64 = (cls_ids[1] == 0) && (cls_ids[3] == 0) &&
                      (cls_ids[5] == 0) && (cls_ids[7] == 0);
    const int cid = is64 ? cls_ids[2 * bb] : cls_ids[bb];
    const float oh = (cid == 1) ? 1.f : 0.f;

    float accs[NT];
    #pragma unroll
    for (int t = 0; t < NT; ++t) accs[t] = 0.f;

    const float* hb = g_hs + (size_t)bb * HSP * FC + c;
    for (int o = 0; o < HSP; ++o) {
        const float h = hb[(size_t)o * FC];
        #pragma unroll
        for (int t = 0; t < NT; ++t) accs[t] = fmaf(w[t][o], h, accs[t]);
    }
    float* ob = out + DENSE_TOTAL + ((size_t)bb * NT) * FC + c;
    #pragma unroll
    for (int t = 0; t < NT; ++t) {
        const float emb = oh * e_pos[t * FC + c] + (1.f - oh) * e_neg[t * FC + c];
        ob[(size_t)t * FC] = accs[t] + bs2[t] + emb;
    }
}

// ---------------------------------------------------------------------------
// Launch
// ---------------------------------------------------------------------------
extern "C" void kernel_launch(void* const* d_in, const int* in_sizes, int n_in,
                              void* d_out, int out_size)
{
    // inputs: feat, prototypes, cls_ids, [num_classes], w_d1, b_d1, w_d2, b_d2,
    //         w_s1, b_s1, w_s2, b_s2, emb_neg, emb_pos
    const int off = (n_in >= 14) ? 1 : 0;   // num_classes scalar present or not
    const float* feat  = (const float*)d_in[0];
    const float* proto = (const float*)d_in[1];
    const int*   cls   = (const int*)  d_in[2];
    const float* w_d1  = (const float*)d_in[3 + off];
    const float* b_d1  = (const float*)d_in[4 + off];
    const float* w_d2  = (const float*)d_in[5 + off];
    const float* b_d2  = (const float*)d_in[6 + off];
    const float* w_s1  = (const float*)d_in[7 + off];
    const float* b_s1  = (const float*)d_in[8 + off];
    const float* w_s2  = (const float*)d_in[9 + off];
    const float* b_s2  = (const float*)d_in[10 + off];
    const float* e_neg = (const float*)d_in[11 + off];
    const float* e_pos = (const float*)d_in[12 + off];
    float* out = (float*)d_out;

    cudaFuncSetAttribute(k_dense, cudaFuncAttributeMaxDynamicSharedMemorySize, 83968);

    k_scale<<<(NB * HW) / 8, 256>>>(feat, proto);
    {
        const int total = 2 * OD * FC + HSP * HW;   // 589824
        k_prep<<<(total + 255) / 256, 256>>>(w_d1, w_d2, w_s1);
    }
    k_dense<<<NB * (HW / 128), 256, 83968>>>(feat, b_d1, b_d2, out);
    k_sparse1<<<dim3(2, KS_SPLIT, NB), 256>>>(feat);
    k_hsreduce<<<((NB * HSP * FC) + 255) / 256, 256>>>(b_s1);
    k_sparse2<<<NB, 256>>>(w_s2, b_s2, e_neg, e_pos, cls, out);
}

// round 5
// speedup vs baseline: 1.4925x; 1.4925x over previous
#include <cuda_runtime.h>
#include <cuda_bf16.h>
#include <cstdint>

// ---------------------------------------------------------------------------
// Shapes
// ---------------------------------------------------------------------------
#define NB   32
#define HW   4096
#define FC   256
#define OD   128
#define O2   256
#define HSP  128
#define NT   8
#define SPLIT 4

#define DENSE_TOTAL ((size_t)NB * O2 * HW)

// ---------------------------------------------------------------------------
// Scratch (device globals)
// ---------------------------------------------------------------------------
__device__ float g_scale[NB * HW];
__device__ unsigned short g_w1h[OD * FC],  g_w1l[OD * FC];     // bf16 hi/lo, row-major [o][c]
__device__ unsigned short g_w2h[O2 * OD],  g_w2l[O2 * OD];     // [o2][o]
__device__ unsigned short g_ws1h[HSP * HW], g_ws1l[HSP * HW];  // [o][p]
__device__ float g_hsp[(size_t)SPLIT * NB * FC * HSP];         // [ks][bb][c][o]
__device__ float g_hs[(size_t)NB * FC * HSP];                  // [bb][c][o]

// ---------------------------------------------------------------------------
// Helpers
// ---------------------------------------------------------------------------
__device__ __forceinline__ uint32_t s2u(const void* p) {
    uint32_t a;
    asm("{ .reg .u64 t; cvta.to.shared.u64 t, %1; cvt.u32.u64 %0, t; }" : "=r"(a) : "l"(p));
    return a;
}

#define LDSM4(r0, r1, r2, r3, addr)                                             \
    asm volatile("ldmatrix.sync.aligned.m8n8.x4.shared.b16 {%0,%1,%2,%3}, [%4];"\
                 : "=r"(r0), "=r"(r1), "=r"(r2), "=r"(r3) : "r"(addr))

__device__ __forceinline__ void mma_bf(float* c, const uint32_t* a,
                                       uint32_t b0, uint32_t b1) {
    asm volatile(
        "mma.sync.aligned.m16n8k16.row.col.f32.bf16.bf16.f32 "
        "{%0,%1,%2,%3},{%4,%5,%6,%7},{%8,%9},{%0,%1,%2,%3};"
        : "+f"(c[0]), "+f"(c[1]), "+f"(c[2]), "+f"(c[3])
        : "r"(a[0]), "r"(a[1]), "r"(a[2]), "r"(a[3]), "r"(b0), "r"(b1));
}

// bf16 hi/lo split
__device__ __forceinline__ void hilo(float x, unsigned short& h, unsigned short& l) {
    __nv_bfloat16 bh = __float2bfloat16_rn(x);
    h = __bfloat16_as_ushort(bh);
    l = __bfloat16_as_ushort(__float2bfloat16_rn(x - __bfloat162float(bh)));
}
__device__ __forceinline__ void hilo4(float a, float b, float c, float d,
                                      ushort4& h4, ushort4& l4) {
    hilo(a, h4.x, l4.x); hilo(b, h4.y, l4.y); hilo(c, h4.z, l4.z); hilo(d, h4.w, l4.w);
}

// ---------------------------------------------------------------------------
// K0: scale[b,p] = 1 + dot(feat[b,p,:], proto)
// ---------------------------------------------------------------------------
__global__ void k_scale(const float* __restrict__ feat, const float* __restrict__ proto)
{
    __shared__ float pr[FC];
    const int t = threadIdx.x;
    pr[t] = proto[t];
    __syncthreads();
    const int warp = t >> 5, lane = t & 31;
    const int pix = blockIdx.x * 8 + warp;
    const float4* f4 = reinterpret_cast<const float4*>(feat + (size_t)pix * FC);
    float4 a = f4[lane];
    float4 b = f4[lane + 32];
    const int c0 = lane * 4;
    float s = a.x*pr[c0] + a.y*pr[c0+1] + a.z*pr[c0+2] + a.w*pr[c0+3]
            + b.x*pr[128+c0] + b.y*pr[128+c0+1] + b.z*pr[128+c0+2] + b.w*pr[128+c0+3];
    #pragma unroll
    for (int off = 16; off > 0; off >>= 1) s += __shfl_xor_sync(0xFFFFFFFFu, s, off);
    if (lane == 0) g_scale[pix] = 1.0f + s;
}

// ---------------------------------------------------------------------------
// K1: split all weights into bf16 hi/lo, same row-major layouts
// ---------------------------------------------------------------------------
__global__ void k_prep(const float* __restrict__ w_d1, const float* __restrict__ w_d2,
                       const float* __restrict__ w_s1)
{
    const int q = blockIdx.x * 256 + threadIdx.x;   // float4 index
    const float4* src;
    ushort4 *dh, *dl;
    int idx;
    if (q < 8192) {
        src = reinterpret_cast<const float4*>(w_d1);  idx = q;
        dh = reinterpret_cast<ushort4*>(g_w1h);  dl = reinterpret_cast<ushort4*>(g_w1l);
    } else if (q < 16384) {
        src = reinterpret_cast<const float4*>(w_d2);  idx = q - 8192;
        dh = reinterpret_cast<ushort4*>(g_w2h);  dl = reinterpret_cast<ushort4*>(g_w2l);
    } else {
        idx = q - 16384;
        if (idx >= HSP * HW / 4) return;
        src = reinterpret_cast<const float4*>(w_s1);
        dh = reinterpret_cast<ushort4*>(g_ws1h); dl = reinterpret_cast<ushort4*>(g_ws1l);
    }
    const float4 f = src[idx];
    ushort4 h4, l4;
    hilo4(f.x, f.y, f.z, f.w, h4, l4);
    dh[idx] = h4;  dl[idx] = l4;
}

// ---------------------------------------------------------------------------
// K2: dense path via mma.sync.  1 CTA = 128 pixels of one batch.
//   GEMM1: [128p x 256c] x W1[128o x 256c]  -> relu(scale applied in A) -> Hs
//   GEMM2: [128p x 128o] x W2[256o2 x 128o] -> out[b][o2][p]
// 8 warps = 4M x 2N; warp tile 32 x 64; hi/lo bf16, 3 mma products.
// ---------------------------------------------------------------------------
#define PK 72     // pitch (halves) of k64 tiles
#define PH 136    // pitch (halves) of Hs / B2 (k128) tiles
#define PS 132    // pitch (floats) of f32 stage

#define DA_HI  0
#define DA_LO  18432
#define DB_HI  36864
#define DB_LO  55296
#define DHS_HI 73728
#define DHS_LO 108544
#define D_SMEM 143360
#define DB2_HI 0          // aliases A/B region (GEMM2 phase)
#define DB2_LO 34816
#define DSTG   0          // f32 stage, aliases same region after pass mma

__global__ void __launch_bounds__(256, 1)
k_dense(const float* __restrict__ feat, const float* __restrict__ b1,
        const float* __restrict__ b2, float* __restrict__ out)
{
    extern __shared__ char smem[];
    const uint32_t sb = s2u(smem);
    const int tid = threadIdx.x, wid = tid >> 5, lane = tid & 31;
    const int bb = blockIdx.x >> 5;
    const int p0 = (blockIdx.x & 31) << 7;
    const size_t frow0 = ((size_t)bb * HW + p0) * FC;

    const int wm = (wid >> 1) * 32, wn = (wid & 1) * 64;
    const int lr = lane & 7, lg = lane >> 3;
    const int qrow = lane >> 2, qcol = (lane & 3) * 2;

    float acc[2][8][4];
    #pragma unroll
    for (int mi = 0; mi < 2; ++mi)
        #pragma unroll
        for (int f = 0; f < 8; ++f)
            #pragma unroll
            for (int v = 0; v < 4; ++v) acc[mi][f][v] = 0.f;

    // ================= GEMM1: K=256 in 4 chunks of 64 =================
    for (int kc = 0; kc < 4; ++kc) {
        // A: feat*scale -> hi/lo [128p][64c]
        #pragma unroll
        for (int i = 0; i < 8; ++i) {
            const int q = i * 256 + tid;
            const int p = q >> 4, c4 = (q & 15) * 4;
            const float4 f = *reinterpret_cast<const float4*>(feat + frow0 + (size_t)p * FC + kc * 64 + c4);
            const float s = __ldg(&g_scale[bb * HW + p0 + p]);
            ushort4 h4, l4;
            hilo4(f.x * s, f.y * s, f.z * s, f.w * s, h4, l4);
            *reinterpret_cast<ushort4*>(smem + DA_HI + 2 * (p * PK + c4)) = h4;
            *reinterpret_cast<ushort4*>(smem + DA_LO + 2 * (p * PK + c4)) = l4;
        }
        // B: W1 rows [128o][64c]
        #pragma unroll
        for (int i = 0; i < 8; ++i) {
            const int q = i * 256 + tid;
            const int n = q >> 4, c4 = (q & 15) * 4;
            *reinterpret_cast<ushort4*>(smem + DB_HI + 2 * (n * PK + c4)) =
                *reinterpret_cast<const ushort4*>(g_w1h + n * FC + kc * 64 + c4);
            *reinterpret_cast<ushort4*>(smem + DB_LO + 2 * (n * PK + c4)) =
                *reinterpret_cast<const ushort4*>(g_w1l + n * FC + kc * 64 + c4);
        }
        __syncthreads();
        #pragma unroll
        for (int ks = 0; ks < 4; ++ks) {
            const int k0 = ks * 16;
            uint32_t ah[2][4], al[2][4], bh[16], bl[16];
            #pragma unroll
            for (int mi = 0; mi < 2; ++mi) {
                const uint32_t ad = sb + 2 * ((wm + mi * 16 + lr + ((lg & 1) << 3)) * PK + k0 + ((lg >> 1) << 3));
                LDSM4(ah[mi][0], ah[mi][1], ah[mi][2], ah[mi][3], ad + DA_HI);
                LDSM4(al[mi][0], al[mi][1], al[mi][2], al[mi][3], ad + DA_LO);
            }
            #pragma unroll
            for (int nf = 0; nf < 4; ++nf) {
                const uint32_t bd = sb + 2 * ((wn + nf * 16 + lr + ((lg >> 1) << 3)) * PK + k0 + ((lg & 1) << 3));
                LDSM4(bh[nf*4+0], bh[nf*4+1], bh[nf*4+2], bh[nf*4+3], bd + DB_HI);
                LDSM4(bl[nf*4+0], bl[nf*4+1], bl[nf*4+2], bl[nf*4+3], bd + DB_LO);
            }
            #pragma unroll
            for (int mi = 0; mi < 2; ++mi)
                #pragma unroll
                for (int f = 0; f < 8; ++f) {
                    const int bi = (f >> 1) * 4 + (f & 1) * 2;
                    mma_bf(acc[mi][f], ah[mi], bh[bi], bh[bi+1]);
                    mma_bf(acc[mi][f], ah[mi], bl[bi], bl[bi+1]);
                    mma_bf(acc[mi][f], al[mi], bh[bi], bh[bi+1]);
                }
        }
        __syncthreads();
    }

    // ---- epilogue 1: relu(acc + b1) -> Hs hi/lo [128p][128o] pitch PH ----
    #pragma unroll
    for (int mi = 0; mi < 2; ++mi)
        #pragma unroll
        for (int f = 0; f < 8; ++f) {
            const int row = wm + mi * 16 + qrow;
            const int col = wn + f * 8 + qcol;
            const float bv0 = __ldg(&b1[col]), bv1 = __ldg(&b1[col + 1]);
            const float v00 = fmaxf(acc[mi][f][0] + bv0, 0.f);
            const float v01 = fmaxf(acc[mi][f][1] + bv1, 0.f);
            const float v10 = fmaxf(acc[mi][f][2] + bv0, 0.f);
            const float v11 = fmaxf(acc[mi][f][3] + bv1, 0.f);
            unsigned short h0, l0, h1, l1;
            hilo(v00, h0, l0); hilo(v01, h1, l1);
            *reinterpret_cast<uint32_t*>(smem + DHS_HI + 2 * (row * PH + col)) = (uint32_t)h0 | ((uint32_t)h1 << 16);
            *reinterpret_cast<uint32_t*>(smem + DHS_LO + 2 * (row * PH + col)) = (uint32_t)l0 | ((uint32_t)l1 << 16);
            hilo(v10, h0, l0); hilo(v11, h1, l1);
            *reinterpret_cast<uint32_t*>(smem + DHS_HI + 2 * ((row + 8) * PH + col)) = (uint32_t)h0 | ((uint32_t)h1 << 16);
            *reinterpret_cast<uint32_t*>(smem + DHS_LO + 2 * ((row + 8) * PH + col)) = (uint32_t)l0 | ((uint32_t)l1 << 16);
        }
    __syncthreads();

    // ================= GEMM2: two passes of 128 o2, K=128 =================
    #pragma unroll 1
    for (int pass = 0; pass < 2; ++pass) {
        // B2: W2 rows [128 o2][128 o]
        #pragma unroll
        for (int i = 0; i < 16; ++i) {
            const int q = i * 256 + tid;
            const int n = q >> 5, c4 = (q & 31) * 4;
            *reinterpret_cast<ushort4*>(smem + DB2_HI + 2 * (n * PH + c4)) =
                *reinterpret_cast<const ushort4*>(g_w2h + (pass * 128 + n) * OD + c4);
            *reinterpret_cast<ushort4*>(smem + DB2_LO + 2 * (n * PH + c4)) =
                *reinterpret_cast<const ushort4*>(g_w2l + (pass * 128 + n) * OD + c4);
        }
        __syncthreads();

        float a2[2][8][4];
        #pragma unroll
        for (int mi = 0; mi < 2; ++mi)
            #pragma unroll
            for (int f = 0; f < 8; ++f)
                #pragma unroll
                for (int v = 0; v < 4; ++v) a2[mi][f][v] = 0.f;

        #pragma unroll
        for (int ks = 0; ks < 8; ++ks) {
            const int k0 = ks * 16;
            uint32_t ah[2][4], al[2][4], bh[16], bl[16];
            #pragma unroll
            for (int mi = 0; mi < 2; ++mi) {
                const uint32_t ad = sb + 2 * ((wm + mi * 16 + lr + ((lg & 1) << 3)) * PH + k0 + ((lg >> 1) << 3));
                LDSM4(ah[mi][0], ah[mi][1], ah[mi][2], ah[mi][3], ad + DHS_HI);
                LDSM4(al[mi][0], al[mi][1], al[mi][2], al[mi][3], ad + DHS_LO);
            }
            #pragma unroll
            for (int nf = 0; nf < 4; ++nf) {
                const uint32_t bd = sb + 2 * ((wn + nf * 16 + lr + ((lg >> 1) << 3)) * PH + k0 + ((lg & 1) << 3));
                LDSM4(bh[nf*4+0], bh[nf*4+1], bh[nf*4+2], bh[nf*4+3], bd + DB2_HI);
                LDSM4(bl[nf*4+0], bl[nf*4+1], bl[nf*4+2], bl[nf*4+3], bd + DB2_LO);
            }
            #pragma unroll
            for (int mi = 0; mi < 2; ++mi)
                #pragma unroll
                for (int f = 0; f < 8; ++f) {
                    const int bi = (f >> 1) * 4 + (f & 1) * 2;
                    mma_bf(a2[mi][f], ah[mi], bh[bi], bh[bi+1]);
                    mma_bf(a2[mi][f], ah[mi], bl[bi], bl[bi+1]);
                    mma_bf(a2[mi][f], al[mi], bh[bi], bh[bi+1]);
                }
        }
        __syncthreads();   // B2 reads done; stage may overwrite

        // stage [o2][px] f32 + bias
        float* stg = reinterpret_cast<float*>(smem + DSTG);
        #pragma unroll
        for (int mi = 0; mi < 2; ++mi)
            #pragma unroll
            for (int f = 0; f < 8; ++f) {
                const int row = wm + mi * 16 + qrow;       // px
                const int col = wn + f * 8 + qcol;         // o2 (local)
                const float bv0 = __ldg(&b2[pass * 128 + col]);
                const float bv1 = __ldg(&b2[pass * 128 + col + 1]);
                stg[col * PS + row]           = a2[mi][f][0] + bv0;
                stg[(col + 1) * PS + row]     = a2[mi][f][1] + bv1;
                stg[col * PS + row + 8]       = a2[mi][f][2] + bv0;
                stg[(col + 1) * PS + row + 8] = a2[mi][f][3] + bv1;
            }
        __syncthreads();

        // coalesced copy stage -> out[b][o2][p]
        float* ob = out + (size_t)bb * O2 * HW + (size_t)(pass * 128) * HW + p0;
        const int row = tid >> 1, off = (tid & 1) * 64;
        #pragma unroll
        for (int j = 0; j < 16; ++j) {
            const float4 v = *reinterpret_cast<const float4*>(&stg[row * PS + off + j * 4]);
            *reinterpret_cast<float4*>(&ob[(size_t)row * HW + off + j * 4]) = v;
        }
        __syncthreads();
    }
}

// ---------------------------------------------------------------------------
// K3: sparse GEMM via mma.sync, split-K=4, c-tiled.
//   grid (2 ct, 4 ks, 32 bb): D[o][c] = sum_p ws1[o][p]*feat[b][p][c]*scale
//   M=128 o, N=128 c, K=1024 p in 16 chunks of 64.
// ---------------------------------------------------------------------------
#define SA_HI 0
#define SA_LO 18432
#define SB_HI 36864
#define SB_LO 55296
#define S_SMEM 73728

__global__ void __launch_bounds__(256, 1)
k_sparse(const float* __restrict__ feat)
{
    extern __shared__ char smem[];
    const uint32_t sb = s2u(smem);
    const int tid = threadIdx.x, wid = tid >> 5, lane = tid & 31;
    const int ct = blockIdx.x, ksp = blockIdx.y, bb = blockIdx.z;
    const int c0 = ct << 7;
    const int pbase = ksp << 10;

    const int wm = (wid >> 1) * 32, wn = (wid & 1) * 64;
    const int lr = lane & 7, lg = lane >> 3;
    const int qrow = lane >> 2, qcol = (lane & 3) * 2;

    float acc[2][8][4];
    #pragma unroll
    for (int mi = 0; mi < 2; ++mi)
        #pragma unroll
        for (int f = 0; f < 8; ++f)
            #pragma unroll
            for (int v = 0; v < 4; ++v) acc[mi][f][v] = 0.f;

    #pragma unroll 1
    for (int ch = 0; ch < 16; ++ch) {
        const int pc = pbase + ch * 64;
        // A: ws1 [128 o][64 p]
        #pragma unroll
        for (int i = 0; i < 8; ++i) {
            const int q = i * 256 + tid;
            const int o = q >> 4, p4 = (q & 15) * 4;
            *reinterpret_cast<ushort4*>(smem + SA_HI + 2 * (o * PK + p4)) =
                *reinterpret_cast<const ushort4*>(g_ws1h + (size_t)o * HW + pc + p4);
            *reinterpret_cast<ushort4*>(smem + SA_LO + 2 * (o * PK + p4)) =
                *reinterpret_cast<const ushort4*>(g_ws1l + (size_t)o * HW + pc + p4);
        }
        // B: feat^T*scale -> [128 c][64 p]
        #pragma unroll
        for (int i = 0; i < 32; ++i) {
            const int pl = i * 2 + (tid >> 7);
            const int c = tid & 127;
            const float v = feat[((size_t)bb * HW + pc + pl) * FC + c0 + c] *
                            __ldg(&g_scale[bb * HW + pc + pl]);
            unsigned short h, l;
            hilo(v, h, l);
            *reinterpret_cast<unsigned short*>(smem + SB_HI + 2 * (c * PK + pl)) = h;
            *reinterpret_cast<unsigned short*>(smem + SB_LO + 2 * (c * PK + pl)) = l;
        }
        __syncthreads();
        #pragma unroll
        for (int ks = 0; ks < 4; ++ks) {
            const int k0 = ks * 16;
            uint32_t ah[2][4], al[2][4], bh[16], bl[16];
            #pragma unroll
            for (int mi = 0; mi < 2; ++mi) {
                const uint32_t ad = sb + 2 * ((wm + mi * 16 + lr + ((lg & 1) << 3)) * PK + k0 + ((lg >> 1) << 3));
                LDSM4(ah[mi][0], ah[mi][1], ah[mi][2], ah[mi][3], ad + SA_HI);
                LDSM4(al[mi][0], al[mi][1], al[mi][2], al[mi][3], ad + SA_LO);
            }
            #pragma unroll
            for (int nf = 0; nf < 4; ++nf) {
                const uint32_t bd = sb + 2 * ((wn + nf * 16 + lr + ((lg >> 1) << 3)) * PK + k0 + ((lg & 1) << 3));
                LDSM4(bh[nf*4+0], bh[nf*4+1], bh[nf*4+2], bh[nf*4+3], bd + SB_HI);
                LDSM4(bl[nf*4+0], bl[nf*4+1], bl[nf*4+2], bl[nf*4+3], bd + SB_LO);
            }
            #pragma unroll
            for (int mi = 0; mi < 2; ++mi)
                #pragma unroll
                for (int f = 0; f < 8; ++f) {
                    const int bi = (f >> 1) * 4 + (f & 1) * 2;
                    mma_bf(acc[mi][f], ah[mi], bh[bi], bh[bi+1]);
                    mma_bf(acc[mi][f], ah[mi], bl[bi], bl[bi+1]);
                    mma_bf(acc[mi][f], al[mi], bh[bi], bh[bi+1]);
                }
        }
        __syncthreads();
    }

    // stage [c][o] f32, then coalesced copy to g_hsp[ks][bb][c][o]
    float* stg = reinterpret_cast<float*>(smem);
    #pragma unroll
    for (int mi = 0; mi < 2; ++mi)
        #pragma unroll
        for (int f = 0; f < 8; ++f) {
            const int row = wm + mi * 16 + qrow;       // o
            const int col = wn + f * 8 + qcol;         // c (local)
            stg[col * PS + row]           = acc[mi][f][0];
            stg[(col + 1) * PS + row]     = acc[mi][f][1];
            stg[col * PS + row + 8]       = acc[mi][f][2];
            stg[(col + 1) * PS + row + 8] = acc[mi][f][3];
        }
    __syncthreads();
    float* pb = g_hsp + ((size_t)(ksp * NB + bb) * FC + c0) * HSP;
    const int row = tid >> 1, off = (tid & 1) * 64;
    #pragma unroll
    for (int j = 0; j < 16; ++j) {
        const float4 v = *reinterpret_cast<const float4*>(&stg[row * PS + off + j * 4]);
        *reinterpret_cast<float4*>(&pb[(size_t)row * HSP + off + j * 4]) = v;
    }
}

// ---------------------------------------------------------------------------
// K3r: reduce split-K partials + bias + relu   (layout [bb][c][o])
// ---------------------------------------------------------------------------
__global__ void k_hsreduce(const float* __restrict__ b_s1)
{
    const size_t idx = (size_t)blockIdx.x * 256 + threadIdx.x;
    const size_t total = (size_t)NB * FC * HSP;
    if (idx < total) {
        float v = g_hsp[idx] + g_hsp[total + idx] + g_hsp[2 * total + idx] + g_hsp[3 * total + idx];
        const int o = (int)(idx & 127);
        g_hs[idx] = fmaxf(v + __ldg(&b_s1[o]), 0.f);
    }
}

// ---------------------------------------------------------------------------
// K4: sparse layer 2 + embeddings.  g_hs is [bb][c][o].
// ---------------------------------------------------------------------------
__global__ void k_sparse2(const float* __restrict__ ws2, const float* __restrict__ bs2,
                          const float* __restrict__ e_neg, const float* __restrict__ e_pos,
                          const int* __restrict__ cls_ids, float* __restrict__ out)
{
    __shared__ float w[NT][HSP];
    const int bb = blockIdx.x, c = threadIdx.x;
    for (int i = threadIdx.x; i < NT * HSP; i += 256)
        w[i >> 7][i & 127] = ws2[i];
    __syncthreads();

    const bool is64 = (cls_ids[1] == 0) && (cls_ids[3] == 0) &&
                      (cls_ids[5] == 0) && (cls_ids[7] == 0);
    const int cid = is64 ? cls_ids[2 * bb] : cls_ids[bb];
    const float oh = (cid == 1) ? 1.f : 0.f;

    float accs[NT];
    #pragma unroll
    for (int t = 0; t < NT; ++t) accs[t] = 0.f;

    const float4* hb = reinterpret_cast<const float4*>(g_hs + ((size_t)bb * FC + c) * HSP);
    for (int o4 = 0; o4 < 32; ++o4) {
        const float4 h = hb[o4];
        const int o = o4 * 4;
        #pragma unroll
        for (int t = 0; t < NT; ++t)
            accs[t] += w[t][o]*h.x + w[t][o+1]*h.y + w[t][o+2]*h.z + w[t][o+3]*h.w;
    }
    float* ob = out + DENSE_TOTAL + ((size_t)bb * NT) * FC + c;
    #pragma unroll
    for (int t = 0; t < NT; ++t) {
        const float emb = oh * e_pos[t * FC + c] + (1.f - oh) * e_neg[t * FC + c];
        ob[(size_t)t * FC] = accs[t] + bs2[t] + emb;
    }
}

// ---------------------------------------------------------------------------
// Launch
// ---------------------------------------------------------------------------
extern "C" void kernel_launch(void* const* d_in, const int* in_sizes, int n_in,
                              void* d_out, int out_size)
{
    const int off = (n_in >= 14) ? 1 : 0;
    const float* feat  = (const float*)d_in[0];
    const float* proto = (const float*)d_in[1];
    const int*   cls   = (const int*)  d_in[2];
    const float* w_d1  = (const float*)d_in[3 + off];
    const float* b_d1  = (const float*)d_in[4 + off];
    const float* w_d2  = (const float*)d_in[5 + off];
    const float* b_d2  = (const float*)d_in[6 + off];
    const float* w_s1  = (const float*)d_in[7 + off];
    const float* b_s1  = (const float*)d_in[8 + off];
    const float* w_s2  = (const float*)d_in[9 + off];
    const float* b_s2  = (const float*)d_in[10 + off];
    const float* e_neg = (const float*)d_in[11 + off];
    const float* e_pos = (const float*)d_in[12 + off];
    float* out = (float*)d_out;

    cudaFuncSetAttribute(k_dense,  cudaFuncAttributeMaxDynamicSharedMemorySize, D_SMEM);
    cudaFuncSetAttribute(k_sparse, cudaFuncAttributeMaxDynamicSharedMemorySize, S_SMEM);

    k_scale<<<(NB * HW) / 8, 256>>>(feat, proto);
    k_prep<<<576, 256>>>(w_d1, w_d2, w_s1);
    k_dense<<<NB * (HW / 128), 256, D_SMEM>>>(feat, b_d1, b_d2, out);
    k_sparse<<<dim3(2, SPLIT, NB), 256, S_SMEM>>>(feat);
    k_hsreduce<<<(int)(((size_t)NB * FC * HSP + 255) / 256), 256>>>(b_s1);
    k_sparse2<<<NB, 256>>>(w_s2, b_s2, e_neg, e_pos, cls, out);
}

// round 6
// speedup vs baseline: 1.6864x; 1.1299x over previous
#include <cuda_runtime.h>
#include <cuda_bf16.h>
#include <cstdint>

// ---------------------------------------------------------------------------
// Shapes
// ---------------------------------------------------------------------------
#define NB   32
#define HW   4096
#define FC   256
#define OD   128
#define O2   256
#define HSP  128
#define NT   8
#define SPLIT 4

#define DENSE_TOTAL ((size_t)NB * O2 * HW)

// ---------------------------------------------------------------------------
// Scratch (device globals; 16B-aligned for cp.async/ushort4)
// ---------------------------------------------------------------------------
__device__ __align__(16) unsigned short g_fh[(size_t)NB * HW * FC];   // feat*scale bf16 hi
__device__ __align__(16) unsigned short g_fl[(size_t)NB * HW * FC];   // lo
__device__ __align__(16) unsigned short g_w1h[OD * FC],  g_w1l[OD * FC];
__device__ __align__(16) unsigned short g_w2h[O2 * OD],  g_w2l[O2 * OD];
__device__ __align__(16) unsigned short g_ws1h[HSP * HW], g_ws1l[HSP * HW];
__device__ float g_hsp[(size_t)SPLIT * NB * FC * HSP];                // [ks][bb][c][o]
__device__ float g_hs[(size_t)NB * FC * HSP];                         // [bb][c][o]

// ---------------------------------------------------------------------------
// Helpers
// ---------------------------------------------------------------------------
__device__ __forceinline__ uint32_t s2u(const void* p) {
    uint32_t a;
    asm("{ .reg .u64 t; cvta.to.shared.u64 t, %1; cvt.u32.u64 %0, t; }" : "=r"(a) : "l"(p));
    return a;
}

#define LDSM4(r0, r1, r2, r3, addr)                                              \
    asm volatile("ldmatrix.sync.aligned.m8n8.x4.shared.b16 {%0,%1,%2,%3}, [%4];" \
                 : "=r"(r0), "=r"(r1), "=r"(r2), "=r"(r3) : "r"(addr))
#define LDSM4T(r0, r1, r2, r3, addr)                                                   \
    asm volatile("ldmatrix.sync.aligned.m8n8.x4.trans.shared.b16 {%0,%1,%2,%3}, [%4];" \
                 : "=r"(r0), "=r"(r1), "=r"(r2), "=r"(r3) : "r"(addr))

#define CPA16(dst, src) \
    asm volatile("cp.async.cg.shared.global [%0], [%1], 16;" :: "r"(dst), "l"(src))
#define CPA_COMMIT() asm volatile("cp.async.commit_group;" ::: "memory")
#define CPA_WAIT(n)  asm volatile("cp.async.wait_group %0;" :: "n"(n) : "memory")

__device__ __forceinline__ void mma_bf(float* c, const uint32_t* a,
                                       uint32_t b0, uint32_t b1) {
    asm volatile(
        "mma.sync.aligned.m16n8k16.row.col.f32.bf16.bf16.f32 "
        "{%0,%1,%2,%3},{%4,%5,%6,%7},{%8,%9},{%0,%1,%2,%3};"
        : "+f"(c[0]), "+f"(c[1]), "+f"(c[2]), "+f"(c[3])
        : "r"(a[0]), "r"(a[1]), "r"(a[2]), "r"(a[3]), "r"(b0), "r"(b1));
}

__device__ __forceinline__ void hilo(float x, unsigned short& h, unsigned short& l) {
    __nv_bfloat16 bh = __float2bfloat16_rn(x);
    h = __bfloat16_as_ushort(bh);
    l = __bfloat16_as_ushort(__float2bfloat16_rn(x - __bfloat162float(bh)));
}
__device__ __forceinline__ void hilo4(float a, float b, float c, float d,
                                      ushort4& h4, ushort4& l4) {
    hilo(a, h4.x, l4.x); hilo(b, h4.y, l4.y); hilo(c, h4.z, l4.z); hilo(d, h4.w, l4.w);
}

// ---------------------------------------------------------------------------
// K0: featprep — fused scale + bf16 hi/lo split.  Warp per pixel.
//   g_fh/g_fl[b][p][c] = hilo(feat[b][p][c] * (1 + dot(feat[b][p],proto)))
// ---------------------------------------------------------------------------
__global__ void k_featprep(const float* __restrict__ feat, const float* __restrict__ proto)
{
    __shared__ float pr[FC];
    const int t = threadIdx.x;
    pr[t] = proto[t];
    __syncthreads();
    const int warp = t >> 5, lane = t & 31;
    const int pix = blockIdx.x * 8 + warp;
    const float4* f4 = reinterpret_cast<const float4*>(feat + (size_t)pix * FC);
    float4 a = f4[lane];
    float4 b = f4[lane + 32];
    const int c0 = lane * 4;
    float s = a.x*pr[c0] + a.y*pr[c0+1] + a.z*pr[c0+2] + a.w*pr[c0+3]
            + b.x*pr[128+c0] + b.y*pr[128+c0+1] + b.z*pr[128+c0+2] + b.w*pr[128+c0+3];
    #pragma unroll
    for (int off = 16; off > 0; off >>= 1) s += __shfl_xor_sync(0xFFFFFFFFu, s, off);
    s += 1.0f;
    ushort4 h4, l4;
    hilo4(a.x * s, a.y * s, a.z * s, a.w * s, h4, l4);
    reinterpret_cast<ushort4*>(g_fh + (size_t)pix * FC)[lane] = h4;
    reinterpret_cast<ushort4*>(g_fl + (size_t)pix * FC)[lane] = l4;
    hilo4(b.x * s, b.y * s, b.z * s, b.w * s, h4, l4);
    reinterpret_cast<ushort4*>(g_fh + (size_t)pix * FC)[lane + 32] = h4;
    reinterpret_cast<ushort4*>(g_fl + (size_t)pix * FC)[lane + 32] = l4;
}

// ---------------------------------------------------------------------------
// K1: split weights into bf16 hi/lo (row-major unchanged)
// ---------------------------------------------------------------------------
__global__ void k_prep(const float* __restrict__ w_d1, const float* __restrict__ w_d2,
                       const float* __restrict__ w_s1)
{
    const int q = blockIdx.x * 256 + threadIdx.x;
    const float4* src;
    ushort4 *dh, *dl;
    int idx;
    if (q < 8192) {
        src = reinterpret_cast<const float4*>(w_d1);  idx = q;
        dh = reinterpret_cast<ushort4*>(g_w1h);  dl = reinterpret_cast<ushort4*>(g_w1l);
    } else if (q < 16384) {
        src = reinterpret_cast<const float4*>(w_d2);  idx = q - 8192;
        dh = reinterpret_cast<ushort4*>(g_w2h);  dl = reinterpret_cast<ushort4*>(g_w2l);
    } else {
        idx = q - 16384;
        if (idx >= HSP * HW / 4) return;
        src = reinterpret_cast<const float4*>(w_s1);
        dh = reinterpret_cast<ushort4*>(g_ws1h); dl = reinterpret_cast<ushort4*>(g_ws1l);
    }
    const float4 f = src[idx];
    ushort4 h4, l4;
    hilo4(f.x, f.y, f.z, f.w, h4, l4);
    dh[idx] = h4;  dl[idx] = l4;
}

// ---------------------------------------------------------------------------
// K2: dense path.  1 CTA = 128 pixels.  cp.async double-buffered.
//  layout (bytes):
//   A   : [2 stage][hi/lo] 128x72h  -> 0      + s*36864 + hl*18432   (73728)
//   B1  : same                       -> 73728  + s*36864 + hl*18432   (73728)
//   Hs  : [hi/lo] 128x136h           -> 147456 + hl*34816             (69632)
//   B2  : [hi/lo] 128x136h  aliases 0 (GEMM2 phase)
//   STG : f32 128x132       aliases 73728
// ---------------------------------------------------------------------------
#define PK 72
#define PH 136
#define PS 132
#define DA(s, hl)  ((s) * 36864 + (hl) * 18432)
#define DB(s, hl)  (73728 + (s) * 36864 + (hl) * 18432)
#define DHS(hl)    (147456 + (hl) * 34816)
#define DB2(hl)    ((hl) * 34816)
#define DSTG       73728
#define D_SMEM     217088

__global__ void __launch_bounds__(256, 1)
k_dense(const float* __restrict__ b1, const float* __restrict__ b2,
        float* __restrict__ out)
{
    extern __shared__ char smem[];
    const uint32_t sb = s2u(smem);
    const int tid = threadIdx.x, wid = tid >> 5, lane = tid & 31;
    const int bb = blockIdx.x >> 5;
    const int p0 = (blockIdx.x & 31) << 7;
    const size_t fbase = ((size_t)bb * HW + p0) * FC;

    const int wm = (wid >> 1) * 32, wn = (wid & 1) * 64;
    const int lr = lane & 7, lg = lane >> 3;
    const int qrow = lane >> 2, qcol = (lane & 3) * 2;

    float acc[2][8][4];
    #pragma unroll
    for (int mi = 0; mi < 2; ++mi)
        #pragma unroll
        for (int f = 0; f < 8; ++f)
            #pragma unroll
            for (int v = 0; v < 4; ++v) acc[mi][f][v] = 0.f;

    // fill chunk kc into stage s:  A=feat hi/lo [128p][64c], B=W1 [128o][64c]
    auto fill1 = [&](int kc, int s) {
        #pragma unroll
        for (int i = 0; i < 4; ++i) {
            const int idx = i * 256 + tid;
            const int row = idx >> 3, seg = idx & 7;
            const uint32_t d = row * 144 + seg * 16;
            const size_t fo = fbase + (size_t)row * FC + kc * 64 + seg * 8;
            CPA16(sb + DA(s, 0) + d, g_fh + fo);
            CPA16(sb + DA(s, 1) + d, g_fl + fo);
            const int wo = row * FC + kc * 64 + seg * 8;
            CPA16(sb + DB(s, 0) + d, g_w1h + wo);
            CPA16(sb + DB(s, 1) + d, g_w1l + wo);
        }
    };

    fill1(0, 0);
    CPA_COMMIT();
    #pragma unroll 1
    for (int kc = 0; kc < 4; ++kc) {
        if (kc < 3) { fill1(kc + 1, (kc + 1) & 1); CPA_COMMIT(); }
        if (kc < 3) { CPA_WAIT(1); } else { CPA_WAIT(0); }
        __syncthreads();
        const int s = kc & 1;
        #pragma unroll
        for (int ks = 0; ks < 4; ++ks) {
            const int k0 = ks * 16;
            uint32_t ah[2][4], al[2][4];
            #pragma unroll
            for (int mi = 0; mi < 2; ++mi) {
                const uint32_t ad = sb + 2 * ((wm + mi * 16 + lr + ((lg & 1) << 3)) * PK + k0 + ((lg >> 1) << 3));
                LDSM4(ah[mi][0], ah[mi][1], ah[mi][2], ah[mi][3], ad + DA(s, 0));
                LDSM4(al[mi][0], al[mi][1], al[mi][2], al[mi][3], ad + DA(s, 1));
            }
            #pragma unroll
            for (int nf = 0; nf < 4; ++nf) {
                uint32_t bh[4], bl[4];
                const uint32_t bd = sb + 2 * ((wn + nf * 16 + lr + ((lg >> 1) << 3)) * PK + k0 + ((lg & 1) << 3));
                LDSM4(bh[0], bh[1], bh[2], bh[3], bd + DB(s, 0));
                LDSM4(bl[0], bl[1], bl[2], bl[3], bd + DB(s, 1));
                #pragma unroll
                for (int mi = 0; mi < 2; ++mi)
                    #pragma unroll
                    for (int h = 0; h < 2; ++h) {
                        float* c = acc[mi][nf * 2 + h];
                        mma_bf(c, ah[mi], bh[h * 2], bh[h * 2 + 1]);
                        mma_bf(c, ah[mi], bl[h * 2], bl[h * 2 + 1]);
                        mma_bf(c, al[mi], bh[h * 2], bh[h * 2 + 1]);
                    }
            }
        }
        __syncthreads();
    }

    // prefetch B2 pass0 (aliases GEMM1 buffers — free now)
    auto fillB2 = [&](int pass) {
        #pragma unroll
        for (int i = 0; i < 8; ++i) {
            const int idx = i * 256 + tid;
            const int row = idx >> 4, seg = idx & 15;
            const uint32_t d = row * 272 + seg * 16;
            const int wo = (pass * 128 + row) * OD + seg * 8;
            CPA16(sb + DB2(0) + d, g_w2h + wo);
            CPA16(sb + DB2(1) + d, g_w2l + wo);
        }
    };
    fillB2(0);
    CPA_COMMIT();

    // epilogue 1: relu(acc + b1) -> Hs hi/lo [128p][128o]
    #pragma unroll
    for (int mi = 0; mi < 2; ++mi)
        #pragma unroll
        for (int f = 0; f < 8; ++f) {
            const int row = wm + mi * 16 + qrow;
            const int col = wn + f * 8 + qcol;
            const float bv0 = __ldg(&b1[col]), bv1 = __ldg(&b1[col + 1]);
            const float v00 = fmaxf(acc[mi][f][0] + bv0, 0.f);
            const float v01 = fmaxf(acc[mi][f][1] + bv1, 0.f);
            const float v10 = fmaxf(acc[mi][f][2] + bv0, 0.f);
            const float v11 = fmaxf(acc[mi][f][3] + bv1, 0.f);
            unsigned short h0, l0, h1, l1;
            hilo(v00, h0, l0); hilo(v01, h1, l1);
            *reinterpret_cast<uint32_t*>(smem + DHS(0) + 2 * (row * PH + col)) = (uint32_t)h0 | ((uint32_t)h1 << 16);
            *reinterpret_cast<uint32_t*>(smem + DHS(1) + 2 * (row * PH + col)) = (uint32_t)l0 | ((uint32_t)l1 << 16);
            hilo(v10, h0, l0); hilo(v11, h1, l1);
            *reinterpret_cast<uint32_t*>(smem + DHS(0) + 2 * ((row + 8) * PH + col)) = (uint32_t)h0 | ((uint32_t)h1 << 16);
            *reinterpret_cast<uint32_t*>(smem + DHS(1) + 2 * ((row + 8) * PH + col)) = (uint32_t)l0 | ((uint32_t)l1 << 16);
        }
    CPA_WAIT(0);
    __syncthreads();

    // GEMM2: two passes of 128 o2, K=128
    #pragma unroll 1
    for (int pass = 0; pass < 2; ++pass) {
        float a2[2][8][4];
        #pragma unroll
        for (int mi = 0; mi < 2; ++mi)
            #pragma unroll
            for (int f = 0; f < 8; ++f)
                #pragma unroll
                for (int v = 0; v < 4; ++v) a2[mi][f][v] = 0.f;

        #pragma unroll
        for (int ks = 0; ks < 8; ++ks) {
            const int k0 = ks * 16;
            uint32_t ah[2][4], al[2][4];
            #pragma unroll
            for (int mi = 0; mi < 2; ++mi) {
                const uint32_t ad = sb + 2 * ((wm + mi * 16 + lr + ((lg & 1) << 3)) * PH + k0 + ((lg >> 1) << 3));
                LDSM4(ah[mi][0], ah[mi][1], ah[mi][2], ah[mi][3], ad + DHS(0));
                LDSM4(al[mi][0], al[mi][1], al[mi][2], al[mi][3], ad + DHS(1));
            }
            #pragma unroll
            for (int nf = 0; nf < 4; ++nf) {
                uint32_t bh[4], bl[4];
                const uint32_t bd = sb + 2 * ((wn + nf * 16 + lr + ((lg >> 1) << 3)) * PH + k0 + ((lg & 1) << 3));
                LDSM4(bh[0], bh[1], bh[2], bh[3], bd + DB2(0));
                LDSM4(bl[0], bl[1], bl[2], bl[3], bd + DB2(1));
                #pragma unroll
                for (int mi = 0; mi < 2; ++mi)
                    #pragma unroll
                    for (int h = 0; h < 2; ++h) {
                        float* c = a2[mi][nf * 2 + h];
                        mma_bf(c, ah[mi], bh[h * 2], bh[h * 2 + 1]);
                        mma_bf(c, ah[mi], bl[h * 2], bl[h * 2 + 1]);
                        mma_bf(c, al[mi], bh[h * 2], bh[h * 2 + 1]);
                    }
            }
        }
        __syncthreads();
        if (pass == 0) { fillB2(1); CPA_COMMIT(); }   // overlap with epilogue

        // stage [o2][px] f32 + bias  (region 73728, no conflict with B2)
        float* stg = reinterpret_cast<float*>(smem + DSTG);
        #pragma unroll
        for (int mi = 0; mi < 2; ++mi)
            #pragma unroll
            for (int f = 0; f < 8; ++f) {
                const int row = wm + mi * 16 + qrow;
                const int col = wn + f * 8 + qcol;
                const float bv0 = __ldg(&b2[pass * 128 + col]);
                const float bv1 = __ldg(&b2[pass * 128 + col + 1]);
                stg[col * PS + row]           = a2[mi][f][0] + bv0;
                stg[(col + 1) * PS + row]     = a2[mi][f][1] + bv1;
                stg[col * PS + row + 8]       = a2[mi][f][2] + bv0;
                stg[(col + 1) * PS + row + 8] = a2[mi][f][3] + bv1;
            }
        __syncthreads();

        float* ob = out + (size_t)bb * O2 * HW + (size_t)(pass * 128) * HW + p0;
        const int row = tid >> 1, off = (tid & 1) * 64;
        #pragma unroll
        for (int j = 0; j < 16; ++j) {
            const float4 v = *reinterpret_cast<const float4*>(&stg[row * PS + off + j * 4]);
            *reinterpret_cast<float4*>(&ob[(size_t)row * HW + off + j * 4]) = v;
        }
        if (pass == 0) { CPA_WAIT(0); }
        __syncthreads();
    }
}

// ---------------------------------------------------------------------------
// K3: sparse GEMM, cp.async double-buffered, ldmatrix.trans for B.
//  grid (2 ct, 4 ks, 32 bb).  D[o][c] = sum_p ws1[o][p]*featsc[b][p][c]
//  A: ws1 [128o][64p] pitch 72 ; B: feat [64p][128c] pitch 136 (trans frags)
//   A: 0     + s*36864 + hl*18432  (73728)
//   B: 73728 + s*34816 + hl*17408  (69632)   -> S_SMEM 143360
// ---------------------------------------------------------------------------
#define SA(s, hl) ((s) * 36864 + (hl) * 18432)
#define SBm(s, hl) (73728 + (s) * 34816 + (hl) * 17408)
#define S_SMEM 143360

__global__ void __launch_bounds__(256, 1)
k_sparse()
{
    extern __shared__ char smem[];
    const uint32_t sb = s2u(smem);
    const int tid = threadIdx.x, wid = tid >> 5, lane = tid & 31;
    const int ct = blockIdx.x, ksp = blockIdx.y, bb = blockIdx.z;
    const int c0 = ct << 7;
    const int pbase = ksp << 10;

    const int wm = (wid >> 1) * 32, wn = (wid & 1) * 64;
    const int lr = lane & 7, lg = lane >> 3;
    const int qrow = lane >> 2, qcol = (lane & 3) * 2;

    float acc[2][8][4];
    #pragma unroll
    for (int mi = 0; mi < 2; ++mi)
        #pragma unroll
        for (int f = 0; f < 8; ++f)
            #pragma unroll
            for (int v = 0; v < 4; ++v) acc[mi][f][v] = 0.f;

    auto fill = [&](int ch, int s) {
        const int pc = pbase + ch * 64;
        #pragma unroll
        for (int i = 0; i < 4; ++i) {
            const int idx = i * 256 + tid;
            // A: [128 o][64 p]
            const int ro = idx >> 3, sa = idx & 7;
            const uint32_t da = ro * 144 + sa * 16;
            const size_t wo = (size_t)ro * HW + pc + sa * 8;
            CPA16(sb + SA(s, 0) + da, g_ws1h + wo);
            CPA16(sb + SA(s, 1) + da, g_ws1l + wo);
            // B: [64 p][128 c]
            const int rp = idx >> 4, sc = idx & 15;
            const uint32_t db = rp * 272 + sc * 16;
            const size_t fo = ((size_t)bb * HW + pc + rp) * FC + c0 + sc * 8;
            CPA16(sb + SBm(s, 0) + db, g_fh + fo);
            CPA16(sb + SBm(s, 1) + db, g_fl + fo);
        }
    };

    fill(0, 0);
    CPA_COMMIT();
    #pragma unroll 1
    for (int ch = 0; ch < 16; ++ch) {
        if (ch < 15) { fill(ch + 1, (ch + 1) & 1); CPA_COMMIT(); }
        if (ch < 15) { CPA_WAIT(1); } else { CPA_WAIT(0); }
        __syncthreads();
        const int s = ch & 1;
        #pragma unroll
        for (int ks = 0; ks < 4; ++ks) {
            const int k0 = ks * 16;
            uint32_t ah[2][4], al[2][4];
            #pragma unroll
            for (int mi = 0; mi < 2; ++mi) {
                const uint32_t ad = sb + 2 * ((wm + mi * 16 + lr + ((lg & 1) << 3)) * PK + k0 + ((lg >> 1) << 3));
                LDSM4(ah[mi][0], ah[mi][1], ah[mi][2], ah[mi][3], ad + SA(s, 0));
                LDSM4(al[mi][0], al[mi][1], al[mi][2], al[mi][3], ad + SA(s, 1));
            }
            #pragma unroll
            for (int nf = 0; nf < 4; ++nf) {
                uint32_t bh[4], bl[4];
                // trans: rows = p(k), cols = c(n)
                const uint32_t bd = sb + (k0 + lr + ((lg & 1) << 3)) * 272
                                  + 2 * (wn + nf * 16 + ((lg >> 1) << 3));
                LDSM4T(bh[0], bh[1], bh[2], bh[3], bd + SBm(s, 0));
                LDSM4T(bl[0], bl[1], bl[2], bl[3], bd + SBm(s, 1));
                #pragma unroll
                for (int mi = 0; mi < 2; ++mi)
                    #pragma unroll
                    for (int h = 0; h < 2; ++h) {
                        float* c = acc[mi][nf * 2 + h];
                        mma_bf(c, ah[mi], bh[h * 2], bh[h * 2 + 1]);
                        mma_bf(c, ah[mi], bl[h * 2], bl[h * 2 + 1]);
                        mma_bf(c, al[mi], bh[h * 2], bh[h * 2 + 1]);
                    }
            }
        }
        __syncthreads();
    }

    // stage [c][o] f32, coalesced copy -> g_hsp[ks][bb][c][o]
    float* stg = reinterpret_cast<float*>(smem);
    #pragma unroll
    for (int mi = 0; mi < 2; ++mi)
        #pragma unroll
        for (int f = 0; f < 8; ++f) {
            const int row = wm + mi * 16 + qrow;   // o
            const int col = wn + f * 8 + qcol;     // c (local)
            stg[col * PS + row]           = acc[mi][f][0];
            stg[(col + 1) * PS + row]     = acc[mi][f][1];
            stg[col * PS + row + 8]       = acc[mi][f][2];
            stg[(col + 1) * PS + row + 8] = acc[mi][f][3];
        }
    __syncthreads();
    float* pb = g_hsp + ((size_t)(ksp * NB + bb) * FC + c0) * HSP;
    const int row = tid >> 1, off = (tid & 1) * 64;
    #pragma unroll
    for (int j = 0; j < 16; ++j) {
        const float4 v = *reinterpret_cast<const float4*>(&stg[row * PS + off + j * 4]);
        *reinterpret_cast<float4*>(&pb[(size_t)row * HSP + off + j * 4]) = v;
    }
}

// ---------------------------------------------------------------------------
// K3r: reduce split-K partials + bias + relu  ([bb][c][o])
// ---------------------------------------------------------------------------
__global__ void k_hsreduce(const float* __restrict__ b_s1)
{
    const size_t idx = (size_t)blockIdx.x * 256 + threadIdx.x;
    const size_t total = (size_t)NB * FC * HSP;
    if (idx < total) {
        float v = g_hsp[idx] + g_hsp[total + idx] + g_hsp[2 * total + idx] + g_hsp[3 * total + idx];
        const int o = (int)(idx & 127);
        g_hs[idx] = fmaxf(v + __ldg(&b_s1[o]), 0.f);
    }
}

// ---------------------------------------------------------------------------
// K4: sparse layer 2 + embeddings.  g_hs is [bb][c][o].
// ---------------------------------------------------------------------------
__global__ void k_sparse2(const float* __restrict__ ws2, const float* __restrict__ bs2,
                          const float* __restrict__ e_neg, const float* __restrict__ e_pos,
                          const int* __restrict__ cls_ids, float* __restrict__ out)
{
    __shared__ float w[NT][HSP];
    const int bb = blockIdx.x, c = threadIdx.x;
    for (int i = threadIdx.x; i < NT * HSP; i += 256)
        w[i >> 7][i & 127] = ws2[i];
    __syncthreads();

    const bool is64 = (cls_ids[1] == 0) && (cls_ids[3] == 0) &&
                      (cls_ids[5] == 0) && (cls_ids[7] == 0);
    const int cid = is64 ? cls_ids[2 * bb] : cls_ids[bb];
    const float oh = (cid == 1) ? 1.f : 0.f;

    float accs[NT];
    #pragma unroll
    for (int t = 0; t < NT; ++t) accs[t] = 0.f;

    const float4* hb = reinterpret_cast<const float4*>(g_hs + ((size_t)bb * FC + c) * HSP);
    for (int o4 = 0; o4 < 32; ++o4) {
        const float4 h = hb[o4];
        const int o = o4 * 4;
        #pragma unroll
        for (int t = 0; t < NT; ++t)
            accs[t] += w[t][o]*h.x + w[t][o+1]*h.y + w[t][o+2]*h.z + w[t][o+3]*h.w;
    }
    float* ob = out + DENSE_TOTAL + ((size_t)bb * NT) * FC + c;
    #pragma unroll
    for (int t = 0; t < NT; ++t) {
        const float emb = oh * e_pos[t * FC + c] + (1.f - oh) * e_neg[t * FC + c];
        ob[(size_t)t * FC] = accs[t] + bs2[t] + emb;
    }
}

// ---------------------------------------------------------------------------
// Launch
// ---------------------------------------------------------------------------
extern "C" void kernel_launch(void* const* d_in, const int* in_sizes, int n_in,
                              void* d_out, int out_size)
{
    const int off = (n_in >= 14) ? 1 : 0;
    const float* feat  = (const float*)d_in[0];
    const float* proto = (const float*)d_in[1];
    const int*   cls   = (const int*)  d_in[2];
    const float* w_d1  = (const float*)d_in[3 + off];
    const float* b_d1  = (const float*)d_in[4 + off];
    const float* w_d2  = (const float*)d_in[5 + off];
    const float* b_d2  = (const float*)d_in[6 + off];
    const float* w_s1  = (const float*)d_in[7 + off];
    const float* b_s1  = (const float*)d_in[8 + off];
    const float* w_s2  = (const float*)d_in[9 + off];
    const float* b_s2  = (const float*)d_in[10 + off];
    const float* e_neg = (const float*)d_in[11 + off];
    const float* e_pos = (const float*)d_in[12 + off];
    float* out = (float*)d_out;

    cudaFuncSetAttribute(k_dense,  cudaFuncAttributeMaxDynamicSharedMemorySize, D_SMEM);
    cudaFuncSetAttribute(k_sparse, cudaFuncAttributeMaxDynamicSharedMemorySize, S_SMEM);

    k_featprep<<<(NB * HW) / 8, 256>>>(feat, proto);
    k_prep<<<576, 256>>>(w_d1, w_d2, w_s1);
    k_dense<<<NB * (HW / 128), 256, D_SMEM>>>(b_d1, b_d2, out);
    k_sparse<<<dim3(2, SPLIT, NB), 256, S_SMEM>>>();
    k_hsreduce<<<(int)(((size_t)NB * FC * HSP + 255) / 256), 256>>>(b_s1);
    k_sparse2<<<NB, 256>>>(w_s2, b_s2, e_neg, e_pos, cls, out);
}